// round 9
// baseline (speedup 1.0000x reference)
#include <cuda_runtime.h>
#include <stdint.h>

// Sparse Adagrad on GB300 (sm_103a) — gather formulation, self-cleaning buckets,
// 2 float4 chunks per thread (MLP_p1=4 front-batched loads).
//
//   m_new[v] = m[v] + sum_i g_i^2
//   w_new[v] = w[v] - lr * (sum_i g_i) / (sqrt(m_new[v]) + eps)
//
// Inverse index map as per-bucket linked lists: g_head[v] holds (row+1) or 0
// (empty). 0-encoding matches static zero-init of __device__ globals; the
// fused kernel resets each consumed head to 0, so every graph replay starts
// from a clean all-zero head array.
//
// Output layout: out[0:V*D] = weights_new, out[V*D:2*V*D] = moments_new.
// indices arrive as int32 (JAX x64 disabled). valid_count=200000 static.

#define EPS 1e-10f
#define D 64
#define PAIRS 8              // 8 threads per row, 2 float4 (32B) each
#define VALID_COUNT 200000
#define V_MAX 500000
#define N_MAX 262144

__device__ int g_head[V_MAX];   // 0 = empty, else gradient_row+1 (zero-init)
__device__ int g_next[N_MAX];   // same encoding: old head value

__global__ void build_lists_kernel(const int* __restrict__ idx)
{
    int i = blockIdx.x * blockDim.x + threadIdx.x;
    if (i >= VALID_COUNT) return;
    int v = idx[i];
    g_next[i] = atomicExch(&g_head[v], i + 1);
}

__global__ void __launch_bounds__(256)
fused_adagrad_kernel(const float4* __restrict__ g,   // [N, 16]
                     const float4* __restrict__ w,   // [V, 16]
                     const float4* __restrict__ m,   // [V, 16]
                     const float* __restrict__ lr_ptr,
                     float4* __restrict__ out_w,     // [V, 16]
                     float4* __restrict__ out_m,     // [V, 16]
                     int V)
{
    long t = (long)blockIdx.x * blockDim.x + threadIdx.x;
    long total = (long)V * PAIRS;
    if (t >= total) return;
    int v = (int)(t >> 3);        // output row
    int p = (int)(t & 7);         // which 32B pair within the row
    long off = (long)v * 16 + p * 2;

    // Front-batched independent streaming loads (evict-first: touch-once).
    float4 m0 = __ldcs(&m[off]);
    float4 m1 = __ldcs(&m[off + 1]);
    float4 w0 = __ldcs(&w[off]);
    float4 w1 = __ldcs(&w[off + 1]);

    int e = g_head[v];            // all 8 lanes of row v are in one warp
    if (e > 0) {
        if (p == 0)
            g_head[v] = 0;        // self-clean for the next graph replay
                                  // (warp program order: loads above precede)
        float4 s0  = make_float4(0.f, 0.f, 0.f, 0.f);
        float4 s1  = make_float4(0.f, 0.f, 0.f, 0.f);
        float4 q0  = make_float4(0.f, 0.f, 0.f, 0.f);
        float4 q1  = make_float4(0.f, 0.f, 0.f, 0.f);
        do {
            int i = e - 1;
            long goff = (long)i * 16 + p * 2;
            float4 g0 = g[goff];
            float4 g1 = g[goff + 1];
            s0.x += g0.x;  s0.y += g0.y;  s0.z += g0.z;  s0.w += g0.w;
            s1.x += g1.x;  s1.y += g1.y;  s1.z += g1.z;  s1.w += g1.w;
            q0.x = fmaf(g0.x, g0.x, q0.x);
            q0.y = fmaf(g0.y, g0.y, q0.y);
            q0.z = fmaf(g0.z, g0.z, q0.z);
            q0.w = fmaf(g0.w, g0.w, q0.w);
            q1.x = fmaf(g1.x, g1.x, q1.x);
            q1.y = fmaf(g1.y, g1.y, q1.y);
            q1.z = fmaf(g1.z, g1.z, q1.z);
            q1.w = fmaf(g1.w, g1.w, q1.w);
            e = g_next[i];
        } while (e > 0);

        m0.x += q0.x;  m0.y += q0.y;  m0.z += q0.z;  m0.w += q0.w;
        m1.x += q1.x;  m1.y += q1.y;  m1.z += q1.z;  m1.w += q1.w;

        float lr = __ldg(lr_ptr);
        w0.x -= lr * s0.x / (sqrtf(m0.x) + EPS);
        w0.y -= lr * s0.y / (sqrtf(m0.y) + EPS);
        w0.z -= lr * s0.z / (sqrtf(m0.z) + EPS);
        w0.w -= lr * s0.w / (sqrtf(m0.w) + EPS);
        w1.x -= lr * s1.x / (sqrtf(m1.x) + EPS);
        w1.y -= lr * s1.y / (sqrtf(m1.y) + EPS);
        w1.z -= lr * s1.z / (sqrtf(m1.z) + EPS);
        w1.w -= lr * s1.w / (sqrtf(m1.w) + EPS);
    }

    // Touch-once streaming stores.
    __stcs(&out_w[off],     w0);
    __stcs(&out_w[off + 1], w1);
    __stcs(&out_m[off],     m0);
    __stcs(&out_m[off + 1], m1);
}

extern "C" void kernel_launch(void* const* d_in, const int* in_sizes, int n_in,
                              void* d_out, int out_size)
{
    const float* gradients = (const float*)d_in[0];   // [N, 64]
    const float* weights   = (const float*)d_in[1];   // [V, 64]
    const float* moments   = (const float*)d_in[2];   // [V, 64]
    const int*   indices   = (const int*)d_in[3];     // [N] int32
    const float* lr        = (const float*)d_in[4];   // scalar

    long VD = (long)in_sizes[1];          // V*D = 32,000,000
    int  V  = (int)(VD / D);              // 500,000
    float* out_w = (float*)d_out;
    float* out_m = (float*)d_out + VD;

    // 1. build per-bucket linked lists (heads all-zero: static init on first
    //    run, self-cleaned by the fused kernel every run)
    build_lists_kernel<<<(VALID_COUNT + 255) / 256, 256>>>(indices);

    // 2. fused gather + update + write (single full pass over output,
    //    4M threads, 32B per array per thread)
    {
        long total = (long)V * PAIRS;     // 4M threads
        int threads = 256;
        int blocks = (int)((total + threads - 1) / threads);
        fused_adagrad_kernel<<<blocks, threads>>>((const float4*)gradients,
                                                  (const float4*)weights,
                                                  (const float4*)moments,
                                                  lr,
                                                  (float4*)out_w,
                                                  (float4*)out_m,
                                                  V);
    }
}

// round 10
// speedup vs baseline: 1.0302x; 1.0302x over previous
#include <cuda_runtime.h>
#include <stdint.h>

// Sparse Adagrad on GB300 (sm_103a) — gather formulation.
//
//   m_new[v] = m[v] + sum_i g_i^2
//   w_new[v] = w[v] - lr * (sum_i g_i) / (sqrt(m_new[v]) + eps)
//
// Inverse index map as per-bucket linked lists: g_head[v] holds (row+1) or 0
// (empty). Heads are cleared each launch by a cudaMemsetAsync node (graph-
// capturable, runs without an SM launch ramp, and warms L2 for the build
// atomics). Fused kernel: 16 threads per row, one float4 each, regs<=32 so
// 8 blocks/SM (the proven bandwidth-optimal shape: 84us @ ~6.1TB/s).
//
// Output layout: out[0:V*D] = weights_new, out[V*D:2*V*D] = moments_new.
// indices arrive as int32 (JAX x64 disabled). valid_count=200000 static.

#define EPS 1e-10f
#define D 64
#define CHUNKS 16            // D/4 float4 chunks per row
#define VALID_COUNT 200000
#define V_MAX 500000
#define N_MAX 262144

__device__ int g_head[V_MAX];   // 0 = empty, else gradient_row+1
__device__ int g_next[N_MAX];   // same encoding: old head value

__global__ void build_lists_kernel(const int* __restrict__ idx)
{
    int i = blockIdx.x * blockDim.x + threadIdx.x;
    if (i >= VALID_COUNT) return;
    int v = idx[i];
    g_next[i] = atomicExch(&g_head[v], i + 1);
}

__global__ void __launch_bounds__(256, 8)
fused_adagrad_kernel(const float4* __restrict__ g,   // [N, 16]
                     const float4* __restrict__ w,   // [V, 16]
                     const float4* __restrict__ m,   // [V, 16]
                     const float* __restrict__ lr_ptr,
                     float4* __restrict__ out_w,     // [V, 16]
                     float4* __restrict__ out_m,     // [V, 16]
                     int V)
{
    long t = (long)blockIdx.x * blockDim.x + threadIdx.x;
    long total = (long)V * CHUNKS;
    if (t >= total) return;
    int v = (int)(t >> 4);        // output row
    int chunk = (int)(t & 15);
    long off = (long)v * CHUNKS + chunk;

    float lr = __ldg(lr_ptr);
    // Touch-once streaming loads (evict-first keeps L2 for g + metadata).
    float4 mv = __ldcs(&m[off]);
    float4 wv = __ldcs(&w[off]);

    int e = g_head[v];            // broadcast across the 16 lanes of this row
    if (e > 0) {
        float4 sg  = make_float4(0.f, 0.f, 0.f, 0.f);
        float4 sg2 = make_float4(0.f, 0.f, 0.f, 0.f);
        do {
            int i = e - 1;
            float4 gv = g[(long)i * CHUNKS + chunk];
            sg.x += gv.x;  sg.y += gv.y;  sg.z += gv.z;  sg.w += gv.w;
            sg2.x = fmaf(gv.x, gv.x, sg2.x);
            sg2.y = fmaf(gv.y, gv.y, sg2.y);
            sg2.z = fmaf(gv.z, gv.z, sg2.z);
            sg2.w = fmaf(gv.w, gv.w, sg2.w);
            e = g_next[i];
        } while (e > 0);

        mv.x += sg2.x;  mv.y += sg2.y;  mv.z += sg2.z;  mv.w += sg2.w;

        wv.x -= lr * sg.x / (sqrtf(mv.x) + EPS);
        wv.y -= lr * sg.y / (sqrtf(mv.y) + EPS);
        wv.z -= lr * sg.z / (sqrtf(mv.z) + EPS);
        wv.w -= lr * sg.w / (sqrtf(mv.w) + EPS);
    }

    __stcs(&out_w[off], wv);
    __stcs(&out_m[off], mv);
}

extern "C" void kernel_launch(void* const* d_in, const int* in_sizes, int n_in,
                              void* d_out, int out_size)
{
    const float* gradients = (const float*)d_in[0];   // [N, 64]
    const float* weights   = (const float*)d_in[1];   // [V, 64]
    const float* moments   = (const float*)d_in[2];   // [V, 64]
    const int*   indices   = (const int*)d_in[3];     // [N] int32
    const float* lr        = (const float*)d_in[4];   // scalar

    long VD = (long)in_sizes[1];          // V*D = 32,000,000
    int  V  = (int)(VD / D);              // 500,000
    float* out_w = (float*)d_out;
    float* out_m = (float*)d_out + VD;

    // 1. clear bucket heads via memset node (no SM launch; warms L2)
    void* head_ptr = nullptr;
    cudaGetSymbolAddress(&head_ptr, g_head);
    cudaMemsetAsync(head_ptr, 0, (size_t)V * sizeof(int));

    // 2. build per-bucket linked lists over valid gradient rows
    build_lists_kernel<<<(VALID_COUNT + 255) / 256, 256>>>(indices);

    // 3. fused gather + update + write (single full pass over output)
    {
        long total = (long)V * CHUNKS;    // 8M threads
        int threads = 256;
        int blocks = (int)((total + threads - 1) / threads);
        fused_adagrad_kernel<<<blocks, threads>>>((const float4*)gradients,
                                                  (const float4*)weights,
                                                  (const float4*)moments,
                                                  lr,
                                                  (float4*)out_w,
                                                  (float4*)out_m,
                                                  V);
    }
}

// round 11
// speedup vs baseline: 1.0348x; 1.0044x over previous
#include <cuda_runtime.h>
#include <stdint.h>

// Sparse Adagrad on GB300 (sm_103a) — gather formulation.
//
//   m_new[v] = m[v] + sum_i g_i^2
//   w_new[v] = w[v] - lr * (sum_i g_i) / (sqrt(m_new[v]) + eps)
//
// Inverse index map as per-bucket linked lists: g_head[v] holds (row+1) or 0
// (empty). Heads are cleared each launch by a vectorized init kernel (one
// int4 store per thread) — measured faster than cudaMemsetAsync because the
// kernel's stores leave g_head L2-resident for build_lists' atomics.
// Fused kernel: 16 threads per row, one float4 each, regs=32 -> 8 blocks/SM
// (proven bandwidth-optimal shape: 82.8us @ ~6.15TB/s).
//
// Output layout: out[0:V*D] = weights_new, out[V*D:2*V*D] = moments_new.
// indices arrive as int32 (JAX x64 disabled). valid_count=200000 static.

#define EPS 1e-10f
#define D 64
#define CHUNKS 16            // D/4 float4 chunks per row
#define VALID_COUNT 200000
#define V_MAX 500000
#define N_MAX 262144

__device__ int g_head[V_MAX];   // 0 = empty, else gradient_row+1
__device__ int g_next[N_MAX];   // same encoding: old head value

__global__ void __launch_bounds__(256)
init_head_kernel(int n4)        // n4 = V/4 int4 elements
{
    int i = blockIdx.x * blockDim.x + threadIdx.x;
    if (i < n4)
        reinterpret_cast<int4*>(g_head)[i] = make_int4(0, 0, 0, 0);
}

__global__ void __launch_bounds__(256)
build_lists_kernel(const int* __restrict__ idx)
{
    int i = blockIdx.x * blockDim.x + threadIdx.x;
    if (i >= VALID_COUNT) return;
    int v = idx[i];
    g_next[i] = atomicExch(&g_head[v], i + 1);
}

__global__ void __launch_bounds__(256, 8)
fused_adagrad_kernel(const float4* __restrict__ g,   // [N, 16]
                     const float4* __restrict__ w,   // [V, 16]
                     const float4* __restrict__ m,   // [V, 16]
                     const float* __restrict__ lr_ptr,
                     float4* __restrict__ out_w,     // [V, 16]
                     float4* __restrict__ out_m,     // [V, 16]
                     int V)
{
    long t = (long)blockIdx.x * blockDim.x + threadIdx.x;
    long total = (long)V * CHUNKS;
    if (t >= total) return;
    int v = (int)(t >> 4);        // output row
    int chunk = (int)(t & 15);
    long off = (long)v * CHUNKS + chunk;

    float lr = __ldg(lr_ptr);
    // Touch-once streaming loads (evict-first keeps L2 for g + metadata).
    float4 mv = __ldcs(&m[off]);
    float4 wv = __ldcs(&w[off]);

    int e = g_head[v];            // broadcast across the 16 lanes of this row
    if (e > 0) {
        float4 sg  = make_float4(0.f, 0.f, 0.f, 0.f);
        float4 sg2 = make_float4(0.f, 0.f, 0.f, 0.f);
        do {
            int i = e - 1;
            float4 gv = g[(long)i * CHUNKS + chunk];
            sg.x += gv.x;  sg.y += gv.y;  sg.z += gv.z;  sg.w += gv.w;
            sg2.x = fmaf(gv.x, gv.x, sg2.x);
            sg2.y = fmaf(gv.y, gv.y, sg2.y);
            sg2.z = fmaf(gv.z, gv.z, sg2.z);
            sg2.w = fmaf(gv.w, gv.w, sg2.w);
            e = g_next[i];
        } while (e > 0);

        mv.x += sg2.x;  mv.y += sg2.y;  mv.z += sg2.z;  mv.w += sg2.w;

        wv.x -= lr * sg.x / (sqrtf(mv.x) + EPS);
        wv.y -= lr * sg.y / (sqrtf(mv.y) + EPS);
        wv.z -= lr * sg.z / (sqrtf(mv.z) + EPS);
        wv.w -= lr * sg.w / (sqrtf(mv.w) + EPS);
    }

    __stcs(&out_w[off], wv);
    __stcs(&out_m[off], mv);
}

extern "C" void kernel_launch(void* const* d_in, const int* in_sizes, int n_in,
                              void* d_out, int out_size)
{
    const float* gradients = (const float*)d_in[0];   // [N, 64]
    const float* weights   = (const float*)d_in[1];   // [V, 64]
    const float* moments   = (const float*)d_in[2];   // [V, 64]
    const int*   indices   = (const int*)d_in[3];     // [N] int32
    const float* lr        = (const float*)d_in[4];   // scalar

    long VD = (long)in_sizes[1];          // V*D = 32,000,000
    int  V  = (int)(VD / D);              // 500,000
    float* out_w = (float*)d_out;
    float* out_m = (float*)d_out + VD;

    // 1. clear bucket heads: one int4 store per thread (2 MB, warms L2)
    {
        int n4 = V / 4;                   // 125,000 (V divisible by 4)
        int threads = 256;
        int blocks = (n4 + threads - 1) / threads;
        init_head_kernel<<<blocks, threads>>>(n4);
    }

    // 2. build per-bucket linked lists over valid gradient rows
    build_lists_kernel<<<(VALID_COUNT + 255) / 256, 256>>>(indices);

    // 3. fused gather + update + write (single full pass over output)
    {
        long total = (long)V * CHUNKS;    // 8M threads
        int threads = 256;
        int blocks = (int)((total + threads - 1) / threads);
        fused_adagrad_kernel<<<blocks, threads>>>((const float4*)gradients,
                                                  (const float4*)weights,
                                                  (const float4*)moments,
                                                  lr,
                                                  (float4*)out_w,
                                                  (float4*)out_m,
                                                  V);
    }
}